// round 1
// baseline (speedup 1.0000x reference)
#include <cuda_runtime.h>
#include <math.h>

#define B_  2
#define T_  1024
#define D_  2048
#define H_  16
#define KVH_ 4
#define DH_ 128
#define REP_ 4

// 1 - LAMBDA_INIT and LAMBDA_INIT, LAMBDA_INIT = 0.8 - 0.6*exp(-0.3)
#define LAMBDA_INIT_F   0.35550906759096927f
#define ONE_MINUS_LI_F  0.64449093240903073f
#define GN_EPS_F        1e-5f
#define SCALE_F         0.08838834764831845f  // 1/sqrt(128)

// ---------------- scratch (static device globals: allocation-free) ----------
static __device__ float g_Q[(size_t)B_*T_*H_*2*DH_];    // (2048, 4096)
static __device__ float g_K[(size_t)B_*T_*KVH_*2*DH_];  // (2048, 1024)
static __device__ float g_V[(size_t)B_*T_*KVH_*2*DH_];  // (2048, 1024)
static __device__ float g_O[(size_t)B_*T_*H_*2*DH_];    // (2048, 4096)
static __device__ float g_lambda;

// ---------------- lambda scalar ---------------------------------------------
__global__ void lambda_kernel(const float* __restrict__ lq1, const float* __restrict__ lk1,
                              const float* __restrict__ lq2, const float* __restrict__ lk2) {
    int lane = threadIdx.x;
    float d1 = 0.f, d2 = 0.f;
    #pragma unroll
    for (int i = 0; i < 4; i++) {
        int idx = lane * 4 + i;
        d1 += lq1[idx] * lk1[idx];
        d2 += lq2[idx] * lk2[idx];
    }
    #pragma unroll
    for (int o = 16; o; o >>= 1) {
        d1 += __shfl_xor_sync(0xffffffffu, d1, o);
        d2 += __shfl_xor_sync(0xffffffffu, d2, o);
    }
    if (lane == 0)
        g_lambda = expf(d1) - expf(d2) + LAMBDA_INIT_F;
}

// ---------------- fp32 SGEMM: C[M,N] = A[M,K] @ B[N,K]^T --------------------
// 128x128 tile, BK=8, 256 threads, 8x8 per thread register blocking.
__global__ void __launch_bounds__(256) gemm_nt(const float* __restrict__ A,
                                               const float* __restrict__ Bm,
                                               float* __restrict__ C,
                                               int M, int N, int K) {
    __shared__ float As[8][128];
    __shared__ float Bs[8][128];

    const int tid = threadIdx.x;
    const int bm = blockIdx.y * 128;
    const int bn = blockIdx.x * 128;
    const int tx = tid & 15;       // 0..15 (N dir)
    const int ty = tid >> 4;       // 0..15 (M dir)
    const int lrow = tid >> 1;     // 0..127
    const int lcol = (tid & 1) * 4;

    const float* Ag = A + (size_t)(bm + lrow) * K + lcol;
    const float* Bg = Bm + (size_t)(bn + lrow) * K + lcol;

    float acc[8][8];
    #pragma unroll
    for (int i = 0; i < 8; i++)
        #pragma unroll
        for (int j = 0; j < 8; j++)
            acc[i][j] = 0.f;

    for (int k0 = 0; k0 < K; k0 += 8) {
        float4 av = *(const float4*)(Ag + k0);
        float4 bv = *(const float4*)(Bg + k0);
        As[lcol + 0][lrow] = av.x;
        As[lcol + 1][lrow] = av.y;
        As[lcol + 2][lrow] = av.z;
        As[lcol + 3][lrow] = av.w;
        Bs[lcol + 0][lrow] = bv.x;
        Bs[lcol + 1][lrow] = bv.y;
        Bs[lcol + 2][lrow] = bv.z;
        Bs[lcol + 3][lrow] = bv.w;
        __syncthreads();

        #pragma unroll
        for (int kk = 0; kk < 8; kk++) {
            float a[8], b[8];
            *(float4*)(a)     = *(const float4*)&As[kk][ty * 4];
            *(float4*)(a + 4) = *(const float4*)&As[kk][ty * 4 + 64];
            *(float4*)(b)     = *(const float4*)&Bs[kk][tx * 4];
            *(float4*)(b + 4) = *(const float4*)&Bs[kk][tx * 4 + 64];
            #pragma unroll
            for (int i = 0; i < 8; i++)
                #pragma unroll
                for (int j = 0; j < 8; j++)
                    acc[i][j] += a[i] * b[j];
        }
        __syncthreads();
    }

    #pragma unroll
    for (int i = 0; i < 8; i++) {
        int m = (i < 4) ? (bm + ty * 4 + i) : (bm + 64 + ty * 4 + i - 4);
        float4 c0 = make_float4(acc[i][0], acc[i][1], acc[i][2], acc[i][3]);
        float4 c1 = make_float4(acc[i][4], acc[i][5], acc[i][6], acc[i][7]);
        *(float4*)&C[(size_t)m * N + bn + tx * 4]      = c0;
        *(float4*)&C[(size_t)m * N + bn + 64 + tx * 4] = c1;
    }
}

// ---------------- RoPE (in place) -------------------------------------------
// X layout: rows of 128 floats; row = ((b*T + t)*NH + h)*2 + s. nheads2 = 2*NH.
__global__ void rope_kernel(float* __restrict__ X, const int* __restrict__ pos,
                            int nheads2, int npairs_total) {
    int idx = blockIdx.x * blockDim.x + threadIdx.x;
    if (idx >= npairs_total) return;
    int i = idx & 63;
    int row = idx >> 6;
    int t = (row / nheads2) % T_;
    float inv = powf(10000.0f, -(float)(2 * i) * (1.0f / 128.0f));
    float ang = (float)pos[t] * inv;
    float s, c;
    sincosf(ang, &s, &c);
    float* p = X + (size_t)row * 128 + 2 * i;
    float x1 = p[0], x2 = p[1];
    p[0] = x1 * c - x2 * s;
    p[1] = x1 * s + x2 * c;
}

// ---------------- dual-softmax flash attention + diff + GroupNorm -----------
// grid: (T/8, B*H). block: 256 threads = 8 warps; warp w handles query row
// q = blockIdx.x*8 + w. K/V staged in smem in 16-key tiles.
__global__ void __launch_bounds__(256) attn_kernel(const float* __restrict__ Q,
                                                   const float* __restrict__ Kg,
                                                   const float* __restrict__ Vg,
                                                   float* __restrict__ O,
                                                   const float* __restrict__ gnw,
                                                   const float* __restrict__ gnb) {
    __shared__ float k1s[16][128];
    __shared__ float k2s[16][128];
    __shared__ float vs[16][256];

    const int bh = blockIdx.y;
    const int b = bh / H_;
    const int h = bh % H_;
    const int kvh = h / REP_;
    const int warp = threadIdx.x >> 5;
    const int lane = threadIdx.x & 31;
    const int q = blockIdx.x * 8 + warp;

    const size_t qbase = ((size_t)(b * T_ + q) * H_ + h) * 256;
    const float4 q1v = *(const float4*)&Q[qbase + lane * 4];
    const float4 q2v = *(const float4*)&Q[qbase + 128 + lane * 4];

    float m1 = -1e30f, m2 = -1e30f, l1 = 0.f, l2 = 0.f;
    float acc1[8], acc2[8];
    #pragma unroll
    for (int m = 0; m < 8; m++) { acc1[m] = 0.f; acc2[m] = 0.f; }

    const int q_hi = blockIdx.x * 8 + 7;
    const int ntiles = q_hi / 16 + 1;

    for (int kt = 0; kt < ntiles; kt++) {
        const int j0 = kt * 16;
        __syncthreads();
        // cooperative tile load: 16 keys x (k1|k2 256 floats + v 256 floats)
        for (int i = threadIdx.x; i < 16 * 64; i += 256) {
            int j = i >> 6;
            int c4 = i & 63;
            size_t kb = ((size_t)(b * T_ + j0 + j) * KVH_ + kvh) * 256;
            float4 kv = *(const float4*)&Kg[kb + c4 * 4];
            if (c4 < 32) *(float4*)&k1s[j][c4 * 4] = kv;
            else         *(float4*)&k2s[j][(c4 - 32) * 4] = kv;
            float4 vv = *(const float4*)&Vg[kb + c4 * 4];
            *(float4*)&vs[j][c4 * 4] = vv;
        }
        __syncthreads();

        const int jmax = min(15, q - j0);
        for (int jj = 0; jj <= jmax; jj++) {
            float4 k1v = *(const float4*)&k1s[jj][lane * 4];
            float4 k2v = *(const float4*)&k2s[jj][lane * 4];
            float d1 = q1v.x * k1v.x + q1v.y * k1v.y + q1v.z * k1v.z + q1v.w * k1v.w;
            float d2 = q2v.x * k2v.x + q2v.y * k2v.y + q2v.z * k2v.z + q2v.w * k2v.w;
            #pragma unroll
            for (int o = 16; o; o >>= 1) {
                d1 += __shfl_xor_sync(0xffffffffu, d1, o);
                d2 += __shfl_xor_sync(0xffffffffu, d2, o);
            }
            float s1 = d1 * SCALE_F;
            float s2 = d2 * SCALE_F;
            float m1n = fmaxf(m1, s1), m2n = fmaxf(m2, s2);
            float c1 = __expf(m1 - m1n), c2 = __expf(m2 - m2n);
            float p1 = __expf(s1 - m1n), p2 = __expf(s2 - m2n);
            l1 = l1 * c1 + p1;
            l2 = l2 * c2 + p2;
            m1 = m1n; m2 = m2n;
            #pragma unroll
            for (int m = 0; m < 8; m++) {
                float vv = vs[jj][lane + 32 * m];
                acc1[m] = acc1[m] * c1 + p1 * vv;
                acc2[m] = acc2[m] * c2 + p2 * vv;
            }
        }
    }

    // epilogue: combine, GroupNorm over 256 channels held by this warp
    const float lam = g_lambda;
    const float r1 = 1.f / l1;
    const float r2 = lam / l2;
    float o[8];
    float sum = 0.f, sumsq = 0.f;
    #pragma unroll
    for (int m = 0; m < 8; m++) {
        o[m] = acc1[m] * r1 - acc2[m] * r2;
        sum += o[m];
        sumsq += o[m] * o[m];
    }
    #pragma unroll
    for (int off = 16; off; off >>= 1) {
        sum   += __shfl_xor_sync(0xffffffffu, sum, off);
        sumsq += __shfl_xor_sync(0xffffffffu, sumsq, off);
    }
    const float mean = sum * (1.f / 256.f);
    const float var = sumsq * (1.f / 256.f) - mean * mean;
    const float rstd = rsqrtf(var + GN_EPS_F);

    const size_t obase = (size_t)(b * T_ + q) * 4096 + h * 256;
    #pragma unroll
    for (int m = 0; m < 8; m++) {
        int c = lane + 32 * m;
        float val = (o[m] - mean) * rstd * gnw[h * 256 + c] + gnb[h * 256 + c];
        O[obase + c] = val * ONE_MINUS_LI_F;
    }
}

// ---------------- host launcher ---------------------------------------------
extern "C" void kernel_launch(void* const* d_in, const int* in_sizes, int n_in,
                              void* d_out, int out_size) {
    const float* x   = (const float*)d_in[0];
    const float* Wq  = (const float*)d_in[1];
    const float* Wk  = (const float*)d_in[2];
    const float* Wv  = (const float*)d_in[3];
    const float* Wo  = (const float*)d_in[4];
    const float* lq1 = (const float*)d_in[5];
    const float* lk1 = (const float*)d_in[6];
    const float* lq2 = (const float*)d_in[7];
    const float* lk2 = (const float*)d_in[8];
    const float* gnw = (const float*)d_in[9];
    const float* gnb = (const float*)d_in[10];
    const int*   pos = (const int*)d_in[11];
    float* out = (float*)d_out;

    float *pQ, *pK, *pV, *pO;
    cudaGetSymbolAddress((void**)&pQ, g_Q);
    cudaGetSymbolAddress((void**)&pK, g_K);
    cudaGetSymbolAddress((void**)&pV, g_V);
    cudaGetSymbolAddress((void**)&pO, g_O);

    const int M = B_ * T_;   // 2048

    lambda_kernel<<<1, 32>>>(lq1, lk1, lq2, lk2);

    // projections: C = X @ W^T
    gemm_nt<<<dim3(4096 / 128, M / 128), 256>>>(x, Wq, pQ, M, 4096, D_);
    gemm_nt<<<dim3(1024 / 128, M / 128), 256>>>(x, Wk, pK, M, 1024, D_);
    gemm_nt<<<dim3(1024 / 128, M / 128), 256>>>(x, Wv, pV, M, 1024, D_);

    // RoPE in place (q1,q2 and k1,k2 each get rope on their 128-dim rows)
    {
        int npq = M * H_ * 2 * 64;   // 4,194,304 pairs
        int npk = M * KVH_ * 2 * 64; // 1,048,576 pairs
        rope_kernel<<<(npq + 255) / 256, 256>>>(pQ, pos, 2 * H_, npq);
        rope_kernel<<<(npk + 255) / 256, 256>>>(pK, pos, 2 * KVH_, npk);
    }

    // attention + diff combine + GroupNorm
    attn_kernel<<<dim3(T_ / 8, B_ * H_), 256>>>(pQ, pK, pV, pO, gnw, gnb);

    // output projection: out = O @ Wo^T
    gemm_nt<<<dim3(D_ / 128, M / 128), 256>>>(pO, Wo, out, M, D_, 4096);
}

// round 2
// speedup vs baseline: 1.5541x; 1.5541x over previous
#include <cuda_runtime.h>
#include <math.h>
#include <stdint.h>

#define B_  2
#define T_  1024
#define D_  2048
#define H_  16
#define KVH_ 4
#define DH_ 128
#define REP_ 4

#define LAMBDA_INIT_F   0.35550906759096927f
#define ONE_MINUS_LI_F  0.64449093240903073f
#define GN_EPS_F        1e-5f
#define SCALE_F         0.08838834764831845f  // 1/sqrt(128)

// ---------------- scratch ----------------------------------------------------
static __device__ float g_Q[(size_t)B_*T_*H_*2*DH_];    // (2048, 4096)
static __device__ float g_K[(size_t)B_*T_*KVH_*2*DH_];  // (2048, 1024)
static __device__ float g_V[(size_t)B_*T_*KVH_*2*DH_];  // (2048, 1024)
static __device__ float g_O[(size_t)B_*T_*H_*2*DH_];    // (2048, 4096)
static __device__ float g_lambda;

// ---------------- helpers ----------------------------------------------------
__device__ __forceinline__ float to_tf32(float x) {
    float r;
    asm("cvt.rna.tf32.f32 %0, %1;" : "=f"(r) : "f"(x));
    return r;
}

__device__ __forceinline__ void mma_tf32(float* c, const uint32_t* a, const uint32_t* b) {
    asm volatile(
        "mma.sync.aligned.m16n8k8.row.col.f32.tf32.tf32.f32 "
        "{%0,%1,%2,%3}, {%4,%5,%6,%7}, {%8,%9}, {%0,%1,%2,%3};"
        : "+f"(c[0]), "+f"(c[1]), "+f"(c[2]), "+f"(c[3])
        : "r"(a[0]), "r"(a[1]), "r"(a[2]), "r"(a[3]), "r"(b[0]), "r"(b[1]));
}

// ---------------- lambda scalar ----------------------------------------------
__global__ void lambda_kernel(const float* __restrict__ lq1, const float* __restrict__ lk1,
                              const float* __restrict__ lq2, const float* __restrict__ lk2) {
    int lane = threadIdx.x;
    float d1 = 0.f, d2 = 0.f;
    #pragma unroll
    for (int i = 0; i < 4; i++) {
        int idx = lane * 4 + i;
        d1 += lq1[idx] * lk1[idx];
        d2 += lq2[idx] * lk2[idx];
    }
    #pragma unroll
    for (int o = 16; o; o >>= 1) {
        d1 += __shfl_xor_sync(0xffffffffu, d1, o);
        d2 += __shfl_xor_sync(0xffffffffu, d2, o);
    }
    if (lane == 0)
        g_lambda = expf(d1) - expf(d2) + LAMBDA_INIT_F;
}

// ---------------- tf32 tensor-core GEMM: C[M,N] = A[M,K] @ B[N,K]^T ----------
// 128x128x32 block tile, 256 threads = 8 warps (2 M x 4 N), warp tile 64x32.
__global__ void __launch_bounds__(256) gemm_tf32(const float* __restrict__ A,
                                                 const float* __restrict__ Bm,
                                                 float* __restrict__ C,
                                                 int M, int N, int K) {
    __shared__ float As[128][36];  // [m][k], pad 4 -> conflict-free frag loads
    __shared__ float Bs[128][36];  // [n][k]

    const int tid  = threadIdx.x;
    const int warp = tid >> 5;
    const int lane = tid & 31;
    const int wm = (warp >> 2) * 64;   // 0 / 64
    const int wn = (warp & 3) * 32;    // 0..96
    const int bm = blockIdx.y * 128;
    const int bn = blockIdx.x * 128;
    const int lr = lane >> 2;          // 0..7
    const int lc = lane & 3;           // 0..3

    float acc[4][4][4];
    #pragma unroll
    for (int mi = 0; mi < 4; mi++)
        #pragma unroll
        for (int ni = 0; ni < 4; ni++)
            #pragma unroll
            for (int r = 0; r < 4; r++)
                acc[mi][ni][r] = 0.f;

    for (int k0 = 0; k0 < K; k0 += 32) {
        // cooperative load: 128 rows x 32 k (8 float4/row) for both A and B
        #pragma unroll
        for (int r = 0; r < 4; r++) {
            int idx = tid + 256 * r;
            int row = idx >> 3;
            int kc  = (idx & 7) * 4;
            float4 av = *(const float4*)&A[(size_t)(bm + row) * K + k0 + kc];
            av.x = to_tf32(av.x); av.y = to_tf32(av.y);
            av.z = to_tf32(av.z); av.w = to_tf32(av.w);
            *(float4*)&As[row][kc] = av;
            float4 bv = *(const float4*)&Bm[(size_t)(bn + row) * K + k0 + kc];
            bv.x = to_tf32(bv.x); bv.y = to_tf32(bv.y);
            bv.z = to_tf32(bv.z); bv.w = to_tf32(bv.w);
            *(float4*)&Bs[row][kc] = bv;
        }
        __syncthreads();

        #pragma unroll
        for (int kk = 0; kk < 4; kk++) {
            uint32_t af[4][4], bf[4][2];
            #pragma unroll
            for (int mi = 0; mi < 4; mi++) {
                af[mi][0] = __float_as_uint(As[wm + mi * 16 + lr]    [kk * 8 + lc]);
                af[mi][1] = __float_as_uint(As[wm + mi * 16 + lr + 8][kk * 8 + lc]);
                af[mi][2] = __float_as_uint(As[wm + mi * 16 + lr]    [kk * 8 + lc + 4]);
                af[mi][3] = __float_as_uint(As[wm + mi * 16 + lr + 8][kk * 8 + lc + 4]);
            }
            #pragma unroll
            for (int ni = 0; ni < 4; ni++) {
                bf[ni][0] = __float_as_uint(Bs[wn + ni * 8 + lr][kk * 8 + lc]);
                bf[ni][1] = __float_as_uint(Bs[wn + ni * 8 + lr][kk * 8 + lc + 4]);
            }
            #pragma unroll
            for (int mi = 0; mi < 4; mi++)
                #pragma unroll
                for (int ni = 0; ni < 4; ni++)
                    mma_tf32(acc[mi][ni], af[mi], bf[ni]);
        }
        __syncthreads();
    }

    // epilogue: D fragment c0,c1 at (lr, 2*lc), c2,c3 at (lr+8, 2*lc)
    #pragma unroll
    for (int mi = 0; mi < 4; mi++) {
        #pragma unroll
        for (int ni = 0; ni < 4; ni++) {
            int r0 = bm + wm + mi * 16 + lr;
            int cc = bn + wn + ni * 8 + 2 * lc;
            float2 lo = make_float2(acc[mi][ni][0], acc[mi][ni][1]);
            float2 hi = make_float2(acc[mi][ni][2], acc[mi][ni][3]);
            *(float2*)&C[(size_t)r0 * N + cc]       = lo;
            *(float2*)&C[(size_t)(r0 + 8) * N + cc] = hi;
        }
    }
}

// ---------------- RoPE (in place) ---------------------------------------------
__global__ void rope_kernel(float* __restrict__ X, const int* __restrict__ pos,
                            int nheads2, int npairs_total) {
    int idx = blockIdx.x * blockDim.x + threadIdx.x;
    if (idx >= npairs_total) return;
    int i = idx & 63;
    int row = idx >> 6;
    int t = (row / nheads2) % T_;
    float inv = powf(10000.0f, -(float)(2 * i) * (1.0f / 128.0f));
    float ang = (float)pos[t] * inv;
    float s, c;
    sincosf(ang, &s, &c);
    float* p = X + (size_t)row * 128 + 2 * i;
    float x1 = p[0], x2 = p[1];
    p[0] = x1 * c - x2 * s;
    p[1] = x1 * s + x2 * c;
}

// ---------------- dual-softmax flash attention + diff + GroupNorm -------------
__global__ void __launch_bounds__(256) attn_kernel(const float* __restrict__ Q,
                                                   const float* __restrict__ Kg,
                                                   const float* __restrict__ Vg,
                                                   float* __restrict__ O,
                                                   const float* __restrict__ gnw,
                                                   const float* __restrict__ gnb) {
    __shared__ float k1s[16][128];
    __shared__ float k2s[16][128];
    __shared__ float vs[16][256];

    const int bh = blockIdx.y;
    const int b = bh / H_;
    const int h = bh % H_;
    const int kvh = h / REP_;
    const int warp = threadIdx.x >> 5;
    const int lane = threadIdx.x & 31;
    const int q = blockIdx.x * 8 + warp;

    const size_t qbase = ((size_t)(b * T_ + q) * H_ + h) * 256;
    const float4 q1v = *(const float4*)&Q[qbase + lane * 4];
    const float4 q2v = *(const float4*)&Q[qbase + 128 + lane * 4];

    float m1 = -1e30f, m2 = -1e30f, l1 = 0.f, l2 = 0.f;
    float acc1[8], acc2[8];
    #pragma unroll
    for (int m = 0; m < 8; m++) { acc1[m] = 0.f; acc2[m] = 0.f; }

    const int q_hi = blockIdx.x * 8 + 7;
    const int ntiles = q_hi / 16 + 1;

    for (int kt = 0; kt < ntiles; kt++) {
        const int j0 = kt * 16;
        __syncthreads();
        for (int i = threadIdx.x; i < 16 * 64; i += 256) {
            int j = i >> 6;
            int c4 = i & 63;
            size_t kb = ((size_t)(b * T_ + j0 + j) * KVH_ + kvh) * 256;
            float4 kv = *(const float4*)&Kg[kb + c4 * 4];
            if (c4 < 32) *(float4*)&k1s[j][c4 * 4] = kv;
            else         *(float4*)&k2s[j][(c4 - 32) * 4] = kv;
            float4 vv = *(const float4*)&Vg[kb + c4 * 4];
            *(float4*)&vs[j][c4 * 4] = vv;
        }
        __syncthreads();

        const int jmax = min(15, q - j0);
        for (int jj = 0; jj <= jmax; jj++) {
            float4 k1v = *(const float4*)&k1s[jj][lane * 4];
            float4 k2v = *(const float4*)&k2s[jj][lane * 4];
            float d1 = q1v.x * k1v.x + q1v.y * k1v.y + q1v.z * k1v.z + q1v.w * k1v.w;
            float d2 = q2v.x * k2v.x + q2v.y * k2v.y + q2v.z * k2v.z + q2v.w * k2v.w;
            #pragma unroll
            for (int o = 16; o; o >>= 1) {
                d1 += __shfl_xor_sync(0xffffffffu, d1, o);
                d2 += __shfl_xor_sync(0xffffffffu, d2, o);
            }
            float s1 = d1 * SCALE_F;
            float s2 = d2 * SCALE_F;
            float m1n = fmaxf(m1, s1), m2n = fmaxf(m2, s2);
            float c1 = __expf(m1 - m1n), c2 = __expf(m2 - m2n);
            float p1 = __expf(s1 - m1n), p2 = __expf(s2 - m2n);
            l1 = l1 * c1 + p1;
            l2 = l2 * c2 + p2;
            m1 = m1n; m2 = m2n;
            #pragma unroll
            for (int m = 0; m < 8; m++) {
                float vv = vs[jj][lane + 32 * m];
                acc1[m] = acc1[m] * c1 + p1 * vv;
                acc2[m] = acc2[m] * c2 + p2 * vv;
            }
        }
    }

    const float lam = g_lambda;
    const float r1 = 1.f / l1;
    const float r2 = lam / l2;
    float o[8];
    float sum = 0.f, sumsq = 0.f;
    #pragma unroll
    for (int m = 0; m < 8; m++) {
        o[m] = acc1[m] * r1 - acc2[m] * r2;
        sum += o[m];
        sumsq += o[m] * o[m];
    }
    #pragma unroll
    for (int off = 16; off; off >>= 1) {
        sum   += __shfl_xor_sync(0xffffffffu, sum, off);
        sumsq += __shfl_xor_sync(0xffffffffu, sumsq, off);
    }
    const float mean = sum * (1.f / 256.f);
    const float var = sumsq * (1.f / 256.f) - mean * mean;
    const float rstd = rsqrtf(var + GN_EPS_F);

    const size_t obase = (size_t)(b * T_ + q) * 4096 + h * 256;
    #pragma unroll
    for (int m = 0; m < 8; m++) {
        int c = lane + 32 * m;
        float val = (o[m] - mean) * rstd * gnw[h * 256 + c] + gnb[h * 256 + c];
        O[obase + c] = val * ONE_MINUS_LI_F;
    }
}

// ---------------- host launcher -----------------------------------------------
extern "C" void kernel_launch(void* const* d_in, const int* in_sizes, int n_in,
                              void* d_out, int out_size) {
    const float* x   = (const float*)d_in[0];
    const float* Wq  = (const float*)d_in[1];
    const float* Wk  = (const float*)d_in[2];
    const float* Wv  = (const float*)d_in[3];
    const float* Wo  = (const float*)d_in[4];
    const float* lq1 = (const float*)d_in[5];
    const float* lk1 = (const float*)d_in[6];
    const float* lq2 = (const float*)d_in[7];
    const float* lk2 = (const float*)d_in[8];
    const float* gnw = (const float*)d_in[9];
    const float* gnb = (const float*)d_in[10];
    const int*   pos = (const int*)d_in[11];
    float* out = (float*)d_out;

    float *pQ, *pK, *pV, *pO;
    cudaGetSymbolAddress((void**)&pQ, g_Q);
    cudaGetSymbolAddress((void**)&pK, g_K);
    cudaGetSymbolAddress((void**)&pV, g_V);
    cudaGetSymbolAddress((void**)&pO, g_O);

    const int M = B_ * T_;   // 2048

    lambda_kernel<<<1, 32>>>(lq1, lk1, lq2, lk2);

    gemm_tf32<<<dim3(4096 / 128, M / 128), 256>>>(x, Wq, pQ, M, 4096, D_);
    gemm_tf32<<<dim3(1024 / 128, M / 128), 256>>>(x, Wk, pK, M, 1024, D_);
    gemm_tf32<<<dim3(1024 / 128, M / 128), 256>>>(x, Wv, pV, M, 1024, D_);

    {
        int npq = M * H_ * 2 * 64;
        int npk = M * KVH_ * 2 * 64;
        rope_kernel<<<(npq + 255) / 256, 256>>>(pQ, pos, 2 * H_, npq);
        rope_kernel<<<(npk + 255) / 256, 256>>>(pK, pos, 2 * KVH_, npk);
    }

    attn_kernel<<<dim3(T_ / 8, B_ * H_), 256>>>(pQ, pK, pV, pO, gnw, gnb);

    gemm_tf32<<<dim3(D_ / 128, M / 128), 256>>>(pO, Wo, out, M, D_, 4096);
}